// round 15
// baseline (speedup 1.0000x reference)
#include <cuda_runtime.h>
#include <cuda_fp16.h>
#include <cuda_bf16.h>

#define SRC_H 512
#define SRC_W 512
#define NCH   3
#define OUT_N 224
#define TOX   32
#define TOY   14
#define NTAP  6
#define NIX   77
#define NIY   36
#define WPITCH 81                 // packed s_w pitch in 8B slots (phys max 80)
#define NTHREADS 256
#define NW     8                  // warps per CTA

#define SH_T   52                 // staged rows capacity
#define SW_PX  96                 // staged pixels per row
#define ROWF  (SRC_W * NCH)
#define IMG3F ((size_t)SRC_H * SRC_W * NCH)
#define TOTF  ((size_t)32 * IMG3F)

// dynamic smem layout (bytes)
#define OFF_SRG 0
#define SZ_SRG  (SH_T * SW_PX * 4)        // 19968  RG plane (half2/px)
#define OFF_SB  (OFF_SRG + SZ_SRG)
#define SZ_SB   (SH_T * SW_PX * 2)        // 9984   B plane (half/px)
#define OFF_WPX (OFF_SRG + SZ_SRG + SZ_SB)// 29952 (8-aligned)
#define SZ_WPX  (NIY * WPITCH * 8)        // 23328  packed warped px (uint2)
#define DYN_BYTES (OFF_WPX + SZ_WPX)      // 53280
// s_t aliases the staging region (dead after stage 1):
// packed uint2, skewed: max phys idx = 35*32+31 + 71 = 1222 -> 9784 B <= 29952 OK
#define OFF_T 0

__device__ __forceinline__ unsigned h2u(__half2 h) {
    return *reinterpret_cast<unsigned*>(&h);
}
__device__ __forceinline__ __half2 u2h(unsigned u) {
    return *reinterpret_cast<__half2*>(&u);
}
__device__ __forceinline__ int skew(int w) { return w + (w >> 4); }

__global__ __launch_bounds__(NTHREADS, 4) void warp_resize_kernel(
    const float* __restrict__ images,   // (32, 512, 512, 3)
    const float* __restrict__ mats,     // (32, 2, 3)
    float* __restrict__ out)            // (32, 224, 224, 3)
{
    extern __shared__ __align__(16) unsigned char dynraw[];
    __half2* s_RG  = (__half2*)(dynraw + OFF_SRG);     // staged RG plane, pitch SW_PX
    __half*  s_B   = (__half*) (dynraw + OFF_SB);      // staged B plane, pitch SW_PX
    uint2*   s_wPX = (uint2*)  (dynraw + OFF_WPX);     // packed warped px, skewed
    uint2*   s_t   = (uint2*)  (dynraw + OFF_T);       // packed x-conv result, skewed

    __shared__ float s_wx[TOX][NTAP];
    __shared__ float s_wy[TOY][NTAP];
    __shared__ int   s_bx[TOX];
    __shared__ int   s_by[TOY];

    const int b    = blockIdx.z;
    const int ox0  = blockIdx.x * TOX;
    const int oy0  = blockIdx.y * TOY;
    const int tid  = threadIdx.x;
    const int wrp  = tid >> 5;
    const int lane = tid & 31;

    const float INV = 512.0f / 224.0f;
    const float SC  = 224.0f / 512.0f;

    const int IX0 = (int)floorf((ox0 + 0.5f) * INV - 0.5f) - 2;
    const int IY0 = (int)floorf((oy0 + 0.5f) * INV - 0.5f) - 2;

    // ---- Resize weights (normalized triangle kernel, jax semantics) ----
    if (tid < TOX) {
        int j = ox0 + tid;
        float sf = (j + 0.5f) * INV - 0.5f;
        int i0 = (int)floorf(sf) - 2;
        float wv[NTAP];
        float sum = 0.0f;
        #pragma unroll
        for (int k = 0; k < NTAP; k++) {
            int i = i0 + k;
            float w = fmaxf(1.0f - fabsf(sf - (float)i) * SC, 0.0f);
            if (i < 0 || i >= SRC_W) w = 0.0f;
            wv[k] = w; sum += w;
        }
        float inv = 1.0f / sum;
        #pragma unroll
        for (int k = 0; k < NTAP; k++) s_wx[tid][k] = wv[k] * inv;
        s_bx[tid] = i0 - IX0;
    } else if (tid < TOX + TOY) {
        int t = tid - TOX;
        int j = oy0 + t;
        float sf = (j + 0.5f) * INV - 0.5f;
        int i0 = (int)floorf(sf) - 2;
        float wv[NTAP];
        float sum = 0.0f;
        #pragma unroll
        for (int k = 0; k < NTAP; k++) {
            int i = i0 + k;
            float w = fmaxf(1.0f - fabsf(sf - (float)i) * SC, 0.0f);
            if (i < 0 || i >= SRC_H) w = 0.0f;
            wv[k] = w; sum += w;
        }
        float inv = 1.0f / sum;
        #pragma unroll
        for (int k = 0; k < NTAP; k++) s_wy[t][k] = wv[k] * inv;
        s_by[t] = i0 - IY0;
    }

    const float* Mp = mats + b * 6;
    const float M00 = __ldg(Mp + 0), M01 = __ldg(Mp + 1), M02 = __ldg(Mp + 2);
    const float M10 = __ldg(Mp + 3), M11 = __ldg(Mp + 4), M12 = __ldg(Mp + 5);

    const float* img = images + (size_t)b * IMG3F;

    // ---- Exact affine bbox of the warped tile's source footprint ----
    const float gy0 = (float)IY0, gy1 = (float)(IY0 + NIY - 1);
    const float gx0 = (float)IX0, gx1 = (float)(IX0 + NIX - 1);

    float sy00 = fmaf(M00, gy0, fmaf(M01, gx0, M02));
    float sy01 = fmaf(M00, gy0, fmaf(M01, gx1, M02));
    float sy10 = fmaf(M00, gy1, fmaf(M01, gx0, M02));
    float sy11 = fmaf(M00, gy1, fmaf(M01, gx1, M02));
    float sx00 = fmaf(M10, gy0, fmaf(M11, gx0, M12));
    float sx01 = fmaf(M10, gy0, fmaf(M11, gx1, M12));
    float sx10 = fmaf(M10, gy1, fmaf(M11, gx0, M12));
    float sx11 = fmaf(M10, gy1, fmaf(M11, gx1, M12));

    float symin = fminf(fminf(sy00, sy01), fminf(sy10, sy11));
    float symax = fmaxf(fmaxf(sy00, sy01), fmaxf(sy10, sy11));
    float sxmin = fminf(fminf(sx00, sx01), fminf(sx10, sx11));
    float sxmax = fmaxf(fmaxf(sx00, sx01), fmaxf(sx10, sx11));

    int fy0 = (int)floorf(symin) - 1;
    int fy1 = (int)floorf(symax) + 2;
    int fx0 = (int)floorf(sxmin) - 1;
    int fx1 = (int)floorf(sxmax) + 2;

    bool interior = (fy0 >= 0) && (fy1 < SRC_H) && (fx0 >= 0) && (fx1 < SRC_W);

    int by0 = max(0, fy0);
    int by1 = min(SRC_H - 1, fy1);
    int bx0 = max(0, fx0) & ~3;            // 4-px align for float4 staging
    int bx1 = min(SRC_W - 1, fx1);

    int hgt = by1 - by0 + 1;
    int wid = bx1 - bx0 + 1;
    bool staged = (hgt > 0) && (wid > 0) && (hgt <= SH_T) && (wid <= SW_PX);

    // ---- Stage source box: fp32 interleaved -> SMEM planar fp16 (RG half2 + B half) ----
    if (staged) {
        size_t base_f = (size_t)b * IMG3F + ((size_t)by0 * SRC_W + bx0) * NCH;
        for (int r = wrp; r < hgt; r += NW) {
            if (lane < 24) {                       // 24 lanes x 4 px = 96 px/row
                size_t fidx = base_f + (size_t)r * ROWF + (size_t)lane * 12;
                float f[12];
                if (fidx + 12 <= TOTF) {
                    const float4* g = (const float4*)(images + fidx);
                    float4 a = g[0], bq = g[1], cq = g[2];
                    f[0]=a.x; f[1]=a.y; f[2]=a.z; f[3]=a.w;
                    f[4]=bq.x; f[5]=bq.y; f[6]=bq.z; f[7]=bq.w;
                    f[8]=cq.x; f[9]=cq.y; f[10]=cq.z; f[11]=cq.w;
                } else {
                    #pragma unroll
                    for (int k = 0; k < 12; k++)
                        f[k] = (fidx + k < TOTF) ? images[fidx + k] : 0.0f;
                }
                uint4 rg;
                rg.x = h2u(__floats2half2_rn(f[0], f[1]));
                rg.y = h2u(__floats2half2_rn(f[3], f[4]));
                rg.z = h2u(__floats2half2_rn(f[6], f[7]));
                rg.w = h2u(__floats2half2_rn(f[9], f[10]));
                uint2 bb;
                bb.x = h2u(__floats2half2_rn(f[2], f[5]));
                bb.y = h2u(__floats2half2_rn(f[8], f[11]));
                *(uint4*)(s_RG + r * SW_PX + lane * 4) = rg;
                *(uint2*)(s_B  + r * SW_PX + lane * 4) = bb;
            }
        }
    }
    __syncthreads();

    // ---- Stage 1: warped tile -> packed uint2 (RG half2 | B half dup) ----
    const float by0f = (float)by0;
    const float bx0f = (float)bx0;

    for (int ty = wrp; ty < NIY; ty += NW) {
        float gy = (float)(IY0 + ty);
        float sybA = fmaf(M00, gy, M02);               // absolute bases
        float sxbA = fmaf(M10, gy, M12);

        if (staged && interior) {
            float sybR = sybA - by0f;
            float sxbR = sxbA - bx0f;
            #pragma unroll
            for (int c = 0; c < 3; c++) {
                int tx = c * 32 + lane;
                if (tx < NIX) {
                    float gx = (float)(IX0 + tx);
                    float syr = fmaf(M01, gx, sybR);
                    float sxr = fmaf(M11, gx, sxbR);
                    float fy = floorf(syr), fxx = floorf(sxr);
                    float ay = syr - fy,   ax = sxr - fxx;
                    int iy = (int)fy, ix = (int)fxx;

                    float oy_ = 1.0f - ay, oxx = 1.0f - ax;
                    float w00 = oy_ * oxx, w01 = oy_ * ax;
                    float w10 = ay * oxx,  w11 = ay * ax;

                    const __half2* r0 = s_RG + iy * SW_PX + ix;
                    __half2 q00 = r0[0], q01 = r0[1];
                    __half2 q10 = r0[SW_PX], q11 = r0[SW_PX + 1];
                    const __half* rb = s_B + iy * SW_PX + ix;
                    __half2 hb0 = __halves2half2(rb[0], rb[1]);
                    __half2 hb1 = __halves2half2(rb[SW_PX], rb[SW_PX + 1]);

                    __half2 aRG = __hmul2(__float2half2_rn(w00), q00);
                    aRG = __hfma2(__float2half2_rn(w01), q01, aRG);
                    aRG = __hfma2(__float2half2_rn(w10), q10, aRG);
                    aRG = __hfma2(__float2half2_rn(w11), q11, aRG);

                    __half2 hw0 = __floats2half2_rn(w00, w01);
                    __half2 hw1 = __floats2half2_rn(w10, w11);
                    __half2 hacc = __hfma2(hw1, hb1, __hmul2(hw0, hb0));
                    __half bl_h = __hadd(__low2half(hacc), __high2half(hacc));

                    uint2 px;
                    px.x = h2u(aRG);
                    px.y = h2u(__half2half2(bl_h));
                    s_wPX[ty * WPITCH + skew(tx)] = px;
                }
            }
        } else if (staged) {
            // border tile: validity-zeroed weights + clamped in-box indices
            #pragma unroll
            for (int c = 0; c < 3; c++) {
                int tx = c * 32 + lane;
                if (tx < NIX) {
                    float gx = (float)(IX0 + tx);
                    float sy = fmaf(M01, gx, sybA);
                    float sx = fmaf(M11, gx, sxbA);
                    float fy = floorf(sy), fxx = floorf(sx);
                    float ay = sy - fy,   ax = sx - fxx;
                    int iy = (int)fy, ix = (int)fxx;
                    int iy1 = iy + 1, ix1 = ix + 1;

                    float wy0 = ((unsigned)iy  < (unsigned)SRC_H) ? (1.0f - ay) : 0.0f;
                    float wy1 = ((unsigned)iy1 < (unsigned)SRC_H) ? ay : 0.0f;
                    float wx0v = ((unsigned)ix  < (unsigned)SRC_W) ? (1.0f - ax) : 0.0f;
                    float wx1v = ((unsigned)ix1 < (unsigned)SRC_W) ? ax : 0.0f;
                    float w00 = wy0 * wx0v, w01 = wy0 * wx1v;
                    float w10 = wy1 * wx0v, w11 = wy1 * wx1v;

                    int ry0 = min(max(iy  - by0, 0), hgt - 1);
                    int ry1 = min(max(iy1 - by0, 0), hgt - 1);
                    int rx0 = min(max(ix  - bx0, 0), wid - 1);
                    int rx1 = min(max(ix1 - bx0, 0), wid - 1);

                    __half2 q00 = s_RG[ry0 * SW_PX + rx0];
                    __half2 q01 = s_RG[ry0 * SW_PX + rx1];
                    __half2 q10 = s_RG[ry1 * SW_PX + rx0];
                    __half2 q11 = s_RG[ry1 * SW_PX + rx1];
                    __half2 hb0 = __halves2half2(s_B[ry0 * SW_PX + rx0], s_B[ry0 * SW_PX + rx1]);
                    __half2 hb1 = __halves2half2(s_B[ry1 * SW_PX + rx0], s_B[ry1 * SW_PX + rx1]);

                    __half2 aRG = __hmul2(__float2half2_rn(w00), q00);
                    aRG = __hfma2(__float2half2_rn(w01), q01, aRG);
                    aRG = __hfma2(__float2half2_rn(w10), q10, aRG);
                    aRG = __hfma2(__float2half2_rn(w11), q11, aRG);

                    __half2 hw0 = __floats2half2_rn(w00, w01);
                    __half2 hw1 = __floats2half2_rn(w10, w11);
                    __half2 hacc = __hfma2(hw1, hb1, __hmul2(hw0, hb0));
                    __half bl_h = __hadd(__low2half(hacc), __high2half(hacc));

                    uint2 px;
                    px.x = h2u(aRG);
                    px.y = h2u(__half2half2(bl_h));
                    s_wPX[ty * WPITCH + skew(tx)] = px;
                }
            }
        } else {
            // fallback: global fp32 gather (correctness safety net)
            #pragma unroll 1
            for (int c = 0; c < 3; c++) {
                int tx = c * 32 + lane;
                if (tx < NIX) {
                    float gx = (float)(IX0 + tx);
                    float sy = fmaf(M01, gx, sybA);
                    float sx = fmaf(M11, gx, sxbA);
                    float fy = floorf(sy), fxx = floorf(sx);
                    float ay = sy - fy,   ax = sx - fxx;
                    int iy = (int)fy, ix = (int)fxx;
                    int iy1 = iy + 1, ix1 = ix + 1;

                    float wy0 = ((unsigned)iy  < (unsigned)SRC_H) ? (1.0f - ay) : 0.0f;
                    float wy1 = ((unsigned)iy1 < (unsigned)SRC_H) ? ay : 0.0f;
                    float wx0v = ((unsigned)ix  < (unsigned)SRC_W) ? (1.0f - ax) : 0.0f;
                    float wx1v = ((unsigned)ix1 < (unsigned)SRC_W) ? ax : 0.0f;
                    float w00 = wy0 * wx0v, w01 = wy0 * wx1v;
                    float w10 = wy1 * wx0v, w11 = wy1 * wx1v;

                    int cy0 = min(max(iy, 0), SRC_H - 1);
                    int cy1 = min(max(iy1, 0), SRC_H - 1);
                    int cx0 = min(max(ix, 0), SRC_W - 1);
                    int cx1 = min(max(ix1, 0), SRC_W - 1);
                    const float* p00 = img + ((size_t)cy0 * SRC_W + cx0) * NCH;
                    const float* p01 = img + ((size_t)cy0 * SRC_W + cx1) * NCH;
                    const float* p10 = img + ((size_t)cy1 * SRC_W + cx0) * NCH;
                    const float* p11 = img + ((size_t)cy1 * SRC_W + cx1) * NCH;
                    float r  = w00 * p00[0] + w01 * p01[0] + w10 * p10[0] + w11 * p11[0];
                    float g  = w00 * p00[1] + w01 * p01[1] + w10 * p10[1] + w11 * p11[1];
                    float bl = w00 * p00[2] + w01 * p01[2] + w10 * p10[2] + w11 * p11[2];

                    uint2 px;
                    px.x = h2u(__floats2half2_rn(r, g));
                    px.y = h2u(__float2half2_rn(bl));
                    s_wPX[ty * WPITCH + skew(tx)] = px;
                }
            }
        }
    }
    __syncthreads();

    // ---- Stage 2: x-convolution (6 taps, fp16 HFMA2 accumulation) ----
    {
        int ox  = tid & 31;                 // invariant across iterations
        int base = s_bx[ox];
        __half2 hw[NTAP];
        int kidx[NTAP];
        #pragma unroll
        for (int k = 0; k < NTAP; k++) {
            hw[k] = __float2half2_rn(s_wx[ox][k]);
            kidx[k] = skew(base + k);
        }
        const __half2 hz = __float2half2_rn(0.0f);
        for (int ty = tid >> 5; ty < NIY; ty += NW) {
            const uint2* row = s_wPX + ty * WPITCH;
            __half2 aRG = hz, aB = hz;
            #pragma unroll
            for (int k = 0; k < NTAP; k++) {
                uint2 px = row[kidx[k]];
                aRG = __hfma2(hw[k], u2h(px.x), aRG);
                aB  = __hfma2(hw[k], u2h(px.y), aB);
            }
            uint2 tv;
            tv.x = h2u(aRG);
            tv.y = h2u(aB);
            s_t[skew(ty * TOX + ox)] = tv;
        }
    }
    __syncthreads();

    // ---- Stage 3: y-convolution (6 taps, fp32 accum, packed skewed reads) + store ----
    {
        int ox = tid & 31;
        for (int oy = tid >> 5; oy < TOY; oy += NW) {
            int base = s_by[oy];
            float a0 = 0.0f, a1 = 0.0f, a2 = 0.0f;
            #pragma unroll
            for (int k = 0; k < NTAP; k++) {
                float w = s_wy[oy][k];
                uint2 tv = s_t[skew((base + k) * TOX + ox)];
                float2 f = __half22float2(u2h(tv.x));
                a0 = fmaf(w, f.x, a0);
                a1 = fmaf(w, f.y, a1);
                a2 = fmaf(w, __half2float(__low2half(u2h(tv.y))), a2);
            }
            float* op = out + (((size_t)b * OUT_N + (oy0 + oy)) * OUT_N + (ox0 + ox)) * NCH;
            op[0] = a0;
            op[1] = a1;
            op[2] = a2;
        }
    }
}

extern "C" void kernel_launch(void* const* d_in, const int* in_sizes, int n_in,
                              void* d_out, int out_size)
{
    const float* images = (const float*)d_in[0];
    const float* mats   = (const float*)d_in[1];
    float* out = (float*)d_out;

    cudaFuncSetAttribute(warp_resize_kernel,
                         cudaFuncAttributeMaxDynamicSharedMemorySize, DYN_BYTES);

    dim3 grid(OUT_N / TOX, OUT_N / TOY, 32);   // 7 x 16 x 32
    warp_resize_kernel<<<grid, NTHREADS, DYN_BYTES>>>(images, mats, out);
}

// round 16
// speedup vs baseline: 1.1335x; 1.1335x over previous
#include <cuda_runtime.h>
#include <cuda_fp16.h>
#include <cuda_bf16.h>

#define SRC_H 512
#define SRC_W 512
#define NCH   3
#define OUT_N 224
#define TOX   32
#define TOY   14
#define NTAP  6
#define NIX   77
#define NIY   36
#define NPX   (NIX * NIY)         // 2772 warped pixels
#define WPITCH 81                 // packed s_w pitch in 8B slots (phys max 80)
#define NTHREADS 256
#define NW     8                  // warps per CTA

#define SH_T   52                 // staged rows capacity
#define SW_PX  96                 // staged pixels per row
#define ROWF  (SRC_W * NCH)
#define IMG3F ((size_t)SRC_H * SRC_W * NCH)
#define TOTF  ((size_t)32 * IMG3F)

// dynamic smem layout (bytes)
#define OFF_SRG 0
#define SZ_SRG  (SH_T * SW_PX * 4)        // 19968  RG plane (half2/px)
#define OFF_SB  (OFF_SRG + SZ_SRG)
#define SZ_SB   (SH_T * SW_PX * 2)        // 9984   B plane (half/px)
#define OFF_WPX (OFF_SRG + SZ_SRG + SZ_SB)// 29952 (8-aligned)
#define SZ_WPX  (NIY * WPITCH * 8)        // 23328  packed warped px (uint2)
#define DYN_BYTES (OFF_WPX + SZ_WPX)      // 53280
// s_t aliases the staging region (dead after stage 1):
// packed uint2, skewed: max phys idx = 1222 -> 9784 B <= 29952 OK
#define OFF_T 0

__device__ __forceinline__ unsigned h2u(__half2 h) {
    return *reinterpret_cast<unsigned*>(&h);
}
__device__ __forceinline__ __half2 u2h(unsigned u) {
    return *reinterpret_cast<__half2*>(&u);
}
__device__ __forceinline__ int skew(int w) { return w + (w >> 4); }
// exact ty = p / 77 for 0 <= p < 2772 (verified at all 77k, 77k+76)
__device__ __forceinline__ int div77(int p) { return (p * 3405) >> 18; }

__global__ __launch_bounds__(NTHREADS, 4) void warp_resize_kernel(
    const float* __restrict__ images,   // (32, 512, 512, 3)
    const float* __restrict__ mats,     // (32, 2, 3)
    float* __restrict__ out)            // (32, 224, 224, 3)
{
    extern __shared__ __align__(16) unsigned char dynraw[];
    __half2* s_RG  = (__half2*)(dynraw + OFF_SRG);     // staged RG plane, pitch SW_PX
    __half*  s_B   = (__half*) (dynraw + OFF_SB);      // staged B plane, pitch SW_PX
    uint2*   s_wPX = (uint2*)  (dynraw + OFF_WPX);     // packed warped px, skewed
    uint2*   s_t   = (uint2*)  (dynraw + OFF_T);       // packed x-conv result, skewed

    __shared__ float s_wx[TOX][NTAP];
    __shared__ float s_wy[TOY][NTAP];
    __shared__ int   s_bx[TOX];
    __shared__ int   s_by[TOY];

    const int b    = blockIdx.z;
    const int ox0  = blockIdx.x * TOX;
    const int oy0  = blockIdx.y * TOY;
    const int tid  = threadIdx.x;
    const int wrp  = tid >> 5;
    const int lane = tid & 31;

    const float INV = 512.0f / 224.0f;
    const float SC  = 224.0f / 512.0f;

    const int IX0 = (int)floorf((ox0 + 0.5f) * INV - 0.5f) - 2;
    const int IY0 = (int)floorf((oy0 + 0.5f) * INV - 0.5f) - 2;

    // ---- Resize weights (normalized triangle kernel, jax semantics) ----
    if (tid < TOX) {
        int j = ox0 + tid;
        float sf = (j + 0.5f) * INV - 0.5f;
        int i0 = (int)floorf(sf) - 2;
        float wv[NTAP];
        float sum = 0.0f;
        #pragma unroll
        for (int k = 0; k < NTAP; k++) {
            int i = i0 + k;
            float w = fmaxf(1.0f - fabsf(sf - (float)i) * SC, 0.0f);
            if (i < 0 || i >= SRC_W) w = 0.0f;
            wv[k] = w; sum += w;
        }
        float inv = 1.0f / sum;
        #pragma unroll
        for (int k = 0; k < NTAP; k++) s_wx[tid][k] = wv[k] * inv;
        s_bx[tid] = i0 - IX0;
    } else if (tid < TOX + TOY) {
        int t = tid - TOX;
        int j = oy0 + t;
        float sf = (j + 0.5f) * INV - 0.5f;
        int i0 = (int)floorf(sf) - 2;
        float wv[NTAP];
        float sum = 0.0f;
        #pragma unroll
        for (int k = 0; k < NTAP; k++) {
            int i = i0 + k;
            float w = fmaxf(1.0f - fabsf(sf - (float)i) * SC, 0.0f);
            if (i < 0 || i >= SRC_H) w = 0.0f;
            wv[k] = w; sum += w;
        }
        float inv = 1.0f / sum;
        #pragma unroll
        for (int k = 0; k < NTAP; k++) s_wy[t][k] = wv[k] * inv;
        s_by[t] = i0 - IY0;
    }

    const float* Mp = mats + b * 6;
    const float M00 = __ldg(Mp + 0), M01 = __ldg(Mp + 1), M02 = __ldg(Mp + 2);
    const float M10 = __ldg(Mp + 3), M11 = __ldg(Mp + 4), M12 = __ldg(Mp + 5);

    const float* img = images + (size_t)b * IMG3F;

    // ---- Exact affine bbox of the warped tile's source footprint ----
    const float gy0 = (float)IY0, gy1 = (float)(IY0 + NIY - 1);
    const float gx0 = (float)IX0, gx1 = (float)(IX0 + NIX - 1);

    float sy00 = fmaf(M00, gy0, fmaf(M01, gx0, M02));
    float sy01 = fmaf(M00, gy0, fmaf(M01, gx1, M02));
    float sy10 = fmaf(M00, gy1, fmaf(M01, gx0, M02));
    float sy11 = fmaf(M00, gy1, fmaf(M01, gx1, M02));
    float sx00 = fmaf(M10, gy0, fmaf(M11, gx0, M12));
    float sx01 = fmaf(M10, gy0, fmaf(M11, gx1, M12));
    float sx10 = fmaf(M10, gy1, fmaf(M11, gx0, M12));
    float sx11 = fmaf(M10, gy1, fmaf(M11, gx1, M12));

    float symin = fminf(fminf(sy00, sy01), fminf(sy10, sy11));
    float symax = fmaxf(fmaxf(sy00, sy01), fmaxf(sy10, sy11));
    float sxmin = fminf(fminf(sx00, sx01), fminf(sx10, sx11));
    float sxmax = fmaxf(fmaxf(sx00, sx01), fmaxf(sx10, sx11));

    int fy0 = (int)floorf(symin) - 1;
    int fy1 = (int)floorf(symax) + 2;
    int fx0 = (int)floorf(sxmin) - 1;
    int fx1 = (int)floorf(sxmax) + 2;

    bool interior = (fy0 >= 0) && (fy1 < SRC_H) && (fx0 >= 0) && (fx1 < SRC_W);

    int by0 = max(0, fy0);
    int by1 = min(SRC_H - 1, fy1);
    int bx0 = max(0, fx0) & ~3;            // 4-px align for float4 staging
    int bx1 = min(SRC_W - 1, fx1);

    int hgt = by1 - by0 + 1;
    int wid = bx1 - bx0 + 1;
    bool staged = (hgt > 0) && (wid > 0) && (hgt <= SH_T) && (wid <= SW_PX);

    // ---- Stage source box: fp32 interleaved -> SMEM planar fp16 (RG half2 + B half) ----
    if (staged) {
        size_t base_f = (size_t)b * IMG3F + ((size_t)by0 * SRC_W + bx0) * NCH;
        for (int r = wrp; r < hgt; r += NW) {
            if (lane < 24) {                       // 24 lanes x 4 px = 96 px/row
                size_t fidx = base_f + (size_t)r * ROWF + (size_t)lane * 12;
                float f[12];
                if (fidx + 12 <= TOTF) {
                    const float4* g = (const float4*)(images + fidx);
                    float4 a = g[0], bq = g[1], cq = g[2];
                    f[0]=a.x; f[1]=a.y; f[2]=a.z; f[3]=a.w;
                    f[4]=bq.x; f[5]=bq.y; f[6]=bq.z; f[7]=bq.w;
                    f[8]=cq.x; f[9]=cq.y; f[10]=cq.z; f[11]=cq.w;
                } else {
                    #pragma unroll
                    for (int k = 0; k < 12; k++)
                        f[k] = (fidx + k < TOTF) ? images[fidx + k] : 0.0f;
                }
                uint4 rg;
                rg.x = h2u(__floats2half2_rn(f[0], f[1]));
                rg.y = h2u(__floats2half2_rn(f[3], f[4]));
                rg.z = h2u(__floats2half2_rn(f[6], f[7]));
                rg.w = h2u(__floats2half2_rn(f[9], f[10]));
                uint2 bb;
                bb.x = h2u(__floats2half2_rn(f[2], f[5]));
                bb.y = h2u(__floats2half2_rn(f[8], f[11]));
                *(uint4*)(s_RG + r * SW_PX + lane * 4) = rg;
                *(uint2*)(s_B  + r * SW_PX + lane * 4) = bb;
            }
        }
    }
    __syncthreads();

    // ---- Stage 1: warped tile -> packed uint2 (RG half2 | B half dup), flat distribution ----
    if (staged && interior) {
        const float C0y = M02 - (float)by0;
        const float C0x = M12 - (float)bx0;
        for (int p0 = wrp * 32; p0 < NPX; p0 += NW * 32) {
            int p = p0 + lane;
            if (p < NPX) {
                int ty = div77(p);
                int tx = p - ty * NIX;
                float gy = (float)(IY0 + ty);
                float gx = (float)(IX0 + tx);
                float syr = fmaf(M01, gx, fmaf(M00, gy, C0y));
                float sxr = fmaf(M11, gx, fmaf(M10, gy, C0x));
                float fy = floorf(syr), fxx = floorf(sxr);
                float ay = syr - fy,   ax = sxr - fxx;
                int iy = (int)fy, ix = (int)fxx;

                float oy_ = 1.0f - ay, oxx = 1.0f - ax;
                float w00 = oy_ * oxx, w01 = oy_ * ax;
                float w10 = ay * oxx,  w11 = ay * ax;

                const __half2* r0 = s_RG + iy * SW_PX + ix;
                __half2 q00 = r0[0], q01 = r0[1];
                __half2 q10 = r0[SW_PX], q11 = r0[SW_PX + 1];
                const __half* rb = s_B + iy * SW_PX + ix;
                __half2 hb0 = __halves2half2(rb[0], rb[1]);
                __half2 hb1 = __halves2half2(rb[SW_PX], rb[SW_PX + 1]);

                __half2 aRG = __hmul2(__float2half2_rn(w00), q00);
                aRG = __hfma2(__float2half2_rn(w01), q01, aRG);
                aRG = __hfma2(__float2half2_rn(w10), q10, aRG);
                aRG = __hfma2(__float2half2_rn(w11), q11, aRG);

                __half2 hw0 = __floats2half2_rn(w00, w01);
                __half2 hw1 = __floats2half2_rn(w10, w11);
                __half2 hacc = __hfma2(hw1, hb1, __hmul2(hw0, hb0));
                __half bl_h = __hadd(__low2half(hacc), __high2half(hacc));

                uint2 px;
                px.x = h2u(aRG);
                px.y = h2u(__half2half2(bl_h));
                s_wPX[ty * WPITCH + skew(tx)] = px;
            }
        }
    } else if (staged) {
        // border tile: validity-zeroed weights + clamped in-box indices
        for (int p0 = wrp * 32; p0 < NPX; p0 += NW * 32) {
            int p = p0 + lane;
            if (p < NPX) {
                int ty = div77(p);
                int tx = p - ty * NIX;
                float gy = (float)(IY0 + ty);
                float gx = (float)(IX0 + tx);
                float sy = fmaf(M01, gx, fmaf(M00, gy, M02));
                float sx = fmaf(M11, gx, fmaf(M10, gy, M12));
                float fy = floorf(sy), fxx = floorf(sx);
                float ay = sy - fy,   ax = sx - fxx;
                int iy = (int)fy, ix = (int)fxx;
                int iy1 = iy + 1, ix1 = ix + 1;

                float wy0 = ((unsigned)iy  < (unsigned)SRC_H) ? (1.0f - ay) : 0.0f;
                float wy1 = ((unsigned)iy1 < (unsigned)SRC_H) ? ay : 0.0f;
                float wx0v = ((unsigned)ix  < (unsigned)SRC_W) ? (1.0f - ax) : 0.0f;
                float wx1v = ((unsigned)ix1 < (unsigned)SRC_W) ? ax : 0.0f;
                float w00 = wy0 * wx0v, w01 = wy0 * wx1v;
                float w10 = wy1 * wx0v, w11 = wy1 * wx1v;

                int ry0 = min(max(iy  - by0, 0), hgt - 1);
                int ry1 = min(max(iy1 - by0, 0), hgt - 1);
                int rx0 = min(max(ix  - bx0, 0), wid - 1);
                int rx1 = min(max(ix1 - bx0, 0), wid - 1);

                __half2 q00 = s_RG[ry0 * SW_PX + rx0];
                __half2 q01 = s_RG[ry0 * SW_PX + rx1];
                __half2 q10 = s_RG[ry1 * SW_PX + rx0];
                __half2 q11 = s_RG[ry1 * SW_PX + rx1];
                __half2 hb0 = __halves2half2(s_B[ry0 * SW_PX + rx0], s_B[ry0 * SW_PX + rx1]);
                __half2 hb1 = __halves2half2(s_B[ry1 * SW_PX + rx0], s_B[ry1 * SW_PX + rx1]);

                __half2 aRG = __hmul2(__float2half2_rn(w00), q00);
                aRG = __hfma2(__float2half2_rn(w01), q01, aRG);
                aRG = __hfma2(__float2half2_rn(w10), q10, aRG);
                aRG = __hfma2(__float2half2_rn(w11), q11, aRG);

                __half2 hw0 = __floats2half2_rn(w00, w01);
                __half2 hw1 = __floats2half2_rn(w10, w11);
                __half2 hacc = __hfma2(hw1, hb1, __hmul2(hw0, hb0));
                __half bl_h = __hadd(__low2half(hacc), __high2half(hacc));

                uint2 px;
                px.x = h2u(aRG);
                px.y = h2u(__half2half2(bl_h));
                s_wPX[ty * WPITCH + skew(tx)] = px;
            }
        }
    } else {
        // fallback: global fp32 gather (correctness safety net)
        for (int p0 = wrp * 32; p0 < NPX; p0 += NW * 32) {
            int p = p0 + lane;
            if (p < NPX) {
                int ty = div77(p);
                int tx = p - ty * NIX;
                float gy = (float)(IY0 + ty);
                float gx = (float)(IX0 + tx);
                float sy = fmaf(M01, gx, fmaf(M00, gy, M02));
                float sx = fmaf(M11, gx, fmaf(M10, gy, M12));
                float fy = floorf(sy), fxx = floorf(sx);
                float ay = sy - fy,   ax = sx - fxx;
                int iy = (int)fy, ix = (int)fxx;
                int iy1 = iy + 1, ix1 = ix + 1;

                float wy0 = ((unsigned)iy  < (unsigned)SRC_H) ? (1.0f - ay) : 0.0f;
                float wy1 = ((unsigned)iy1 < (unsigned)SRC_H) ? ay : 0.0f;
                float wx0v = ((unsigned)ix  < (unsigned)SRC_W) ? (1.0f - ax) : 0.0f;
                float wx1v = ((unsigned)ix1 < (unsigned)SRC_W) ? ax : 0.0f;
                float w00 = wy0 * wx0v, w01 = wy0 * wx1v;
                float w10 = wy1 * wx0v, w11 = wy1 * wx1v;

                int cy0 = min(max(iy, 0), SRC_H - 1);
                int cy1 = min(max(iy1, 0), SRC_H - 1);
                int cx0 = min(max(ix, 0), SRC_W - 1);
                int cx1 = min(max(ix1, 0), SRC_W - 1);
                const float* p00 = img + ((size_t)cy0 * SRC_W + cx0) * NCH;
                const float* p01 = img + ((size_t)cy0 * SRC_W + cx1) * NCH;
                const float* p10 = img + ((size_t)cy1 * SRC_W + cx0) * NCH;
                const float* p11 = img + ((size_t)cy1 * SRC_W + cx1) * NCH;
                float r  = w00 * p00[0] + w01 * p01[0] + w10 * p10[0] + w11 * p11[0];
                float g  = w00 * p00[1] + w01 * p01[1] + w10 * p10[1] + w11 * p11[1];
                float bl = w00 * p00[2] + w01 * p01[2] + w10 * p10[2] + w11 * p11[2];

                uint2 px;
                px.x = h2u(__floats2half2_rn(r, g));
                px.y = h2u(__float2half2_rn(bl));
                s_wPX[ty * WPITCH + skew(tx)] = px;
            }
        }
    }
    __syncthreads();

    // ---- Stage 2: x-convolution (6 taps, fp32 accum, packed skewed I/O) ----
    {
        int ox  = tid & 31;                 // invariant across iterations
        int base = s_bx[ox];
        float w0 = s_wx[ox][0], w1 = s_wx[ox][1], w2 = s_wx[ox][2];
        float w3 = s_wx[ox][3], w4 = s_wx[ox][4], w5 = s_wx[ox][5];
        for (int ty = tid >> 5; ty < NIY; ty += NW) {
            const uint2* row = s_wPX + ty * WPITCH;
            float a0 = 0.0f, a1 = 0.0f, a2 = 0.0f;
            #pragma unroll
            for (int k = 0; k < NTAP; k++) {
                float w = (k == 0) ? w0 : (k == 1) ? w1 : (k == 2) ? w2
                        : (k == 3) ? w3 : (k == 4) ? w4 : w5;
                uint2 px = row[skew(base + k)];
                float2 f = __half22float2(u2h(px.x));
                a0 = fmaf(w, f.x, a0);
                a1 = fmaf(w, f.y, a1);
                a2 = fmaf(w, __half2float(__low2half(u2h(px.y))), a2);
            }
            uint2 tv;
            tv.x = h2u(__floats2half2_rn(a0, a1));
            tv.y = h2u(__float2half2_rn(a2));
            s_t[skew(ty * TOX + ox)] = tv;
        }
    }
    __syncthreads();

    // ---- Stage 3: y-convolution (6 taps, fp32 accum, packed skewed reads) + store ----
    {
        int ox = tid & 31;
        for (int oy = tid >> 5; oy < TOY; oy += NW) {
            int base = s_by[oy];
            float a0 = 0.0f, a1 = 0.0f, a2 = 0.0f;
            #pragma unroll
            for (int k = 0; k < NTAP; k++) {
                float w = s_wy[oy][k];
                uint2 tv = s_t[skew((base + k) * TOX + ox)];
                float2 f = __half22float2(u2h(tv.x));
                a0 = fmaf(w, f.x, a0);
                a1 = fmaf(w, f.y, a1);
                a2 = fmaf(w, __half2float(__low2half(u2h(tv.y))), a2);
            }
            float* op = out + (((size_t)b * OUT_N + (oy0 + oy)) * OUT_N + (ox0 + ox)) * NCH;
            op[0] = a0;
            op[1] = a1;
            op[2] = a2;
        }
    }
}

extern "C" void kernel_launch(void* const* d_in, const int* in_sizes, int n_in,
                              void* d_out, int out_size)
{
    const float* images = (const float*)d_in[0];
    const float* mats   = (const float*)d_in[1];
    float* out = (float*)d_out;

    cudaFuncSetAttribute(warp_resize_kernel,
                         cudaFuncAttributeMaxDynamicSharedMemorySize, DYN_BYTES);

    dim3 grid(OUT_N / TOX, OUT_N / TOY, 32);   // 7 x 16 x 32
    warp_resize_kernel<<<grid, NTHREADS, DYN_BYTES>>>(images, mats, out);
}

// round 17
// speedup vs baseline: 1.1741x; 1.0358x over previous
#include <cuda_runtime.h>
#include <cuda_fp16.h>
#include <cuda_bf16.h>

#define SRC_H 512
#define SRC_W 512
#define NCH   3
#define OUT_N 224
#define TOX   32
#define TOY   14
#define NTAP  5                   // triangle support radius 512/224 -> max 5 nonzero taps
#define NIX   77
#define NIY   36
#define WPITCH 81                 // packed s_w pitch in 8B slots (phys max 80)
#define NTHREADS 256
#define NW     8                  // warps per CTA

#define SH_T   52                 // staged rows capacity
#define SW_PX  96                 // staged pixels per row
#define ROWF  (SRC_W * NCH)
#define IMG3F ((size_t)SRC_H * SRC_W * NCH)
#define TOTF  ((size_t)32 * IMG3F)

// dynamic smem layout (bytes)
#define OFF_SRG 0
#define SZ_SRG  (SH_T * SW_PX * 4)        // 19968  RG plane (half2/px)
#define OFF_SB  (OFF_SRG + SZ_SRG)
#define SZ_SB   (SH_T * SW_PX * 2)        // 9984   B plane (half/px)
#define OFF_WPX (OFF_SRG + SZ_SRG + SZ_SB)// 29952 (8-aligned)
#define SZ_WPX  (NIY * WPITCH * 8)        // 23328  packed warped px (uint2)
#define DYN_BYTES (OFF_WPX + SZ_WPX)      // 53280
// s_t aliases the staging region (dead after stage 1):
// packed uint2, skewed: max phys idx = 1222 -> 9784 B <= 29952 OK
#define OFF_T 0

__device__ __forceinline__ unsigned h2u(__half2 h) {
    return *reinterpret_cast<unsigned*>(&h);
}
__device__ __forceinline__ __half2 u2h(unsigned u) {
    return *reinterpret_cast<__half2*>(&u);
}
__device__ __forceinline__ int skew(int w) { return w + (w >> 4); }

__global__ __launch_bounds__(NTHREADS, 4) void warp_resize_kernel(
    const float* __restrict__ images,   // (32, 512, 512, 3)
    const float* __restrict__ mats,     // (32, 2, 3)
    float* __restrict__ out)            // (32, 224, 224, 3)
{
    extern __shared__ __align__(16) unsigned char dynraw[];
    __half2* s_RG  = (__half2*)(dynraw + OFF_SRG);     // staged RG plane, pitch SW_PX
    __half*  s_B   = (__half*) (dynraw + OFF_SB);      // staged B plane, pitch SW_PX
    uint2*   s_wPX = (uint2*)  (dynraw + OFF_WPX);     // packed warped px, skewed
    uint2*   s_t   = (uint2*)  (dynraw + OFF_T);       // packed x-conv result, skewed

    __shared__ float s_wx[TOX][NTAP];
    __shared__ float s_wy[TOY][NTAP];
    __shared__ int   s_bx[TOX];
    __shared__ int   s_by[TOY];

    const int b    = blockIdx.z;
    const int ox0  = blockIdx.x * TOX;
    const int oy0  = blockIdx.y * TOY;
    const int tid  = threadIdx.x;
    const int wrp  = tid >> 5;
    const int lane = tid & 31;

    const float INV = 512.0f / 224.0f;
    const float SC  = 224.0f / 512.0f;

    const int IX0 = (int)floorf((ox0 + 0.5f) * INV - 0.5f) - 2;
    const int IY0 = (int)floorf((oy0 + 0.5f) * INV - 0.5f) - 2;

    // ---- Resize weights (normalized triangle kernel, jax semantics) ----
    // 6-tap jax-exact window, then drop the provably-zero end tap -> 5 taps.
    if (tid < TOX) {
        int j = ox0 + tid;
        float sf = (j + 0.5f) * INV - 0.5f;
        int i0 = (int)floorf(sf) - 2;
        float wv[6];
        float sum = 0.0f;
        #pragma unroll
        for (int k = 0; k < 6; k++) {
            int i = i0 + k;
            float w = fmaxf(1.0f - fabsf(sf - (float)i) * SC, 0.0f);
            if (i < 0 || i >= SRC_W) w = 0.0f;
            wv[k] = w; sum += w;
        }
        float inv = 1.0f / sum;
        int shift = (wv[0] > 0.0f) ? 0 : 1;
        #pragma unroll
        for (int k = 0; k < NTAP; k++) s_wx[tid][k] = wv[k + shift] * inv;
        s_bx[tid] = i0 + shift - IX0;
    } else if (tid < TOX + TOY) {
        int t = tid - TOX;
        int j = oy0 + t;
        float sf = (j + 0.5f) * INV - 0.5f;
        int i0 = (int)floorf(sf) - 2;
        float wv[6];
        float sum = 0.0f;
        #pragma unroll
        for (int k = 0; k < 6; k++) {
            int i = i0 + k;
            float w = fmaxf(1.0f - fabsf(sf - (float)i) * SC, 0.0f);
            if (i < 0 || i >= SRC_H) w = 0.0f;
            wv[k] = w; sum += w;
        }
        float inv = 1.0f / sum;
        int shift = (wv[0] > 0.0f) ? 0 : 1;
        #pragma unroll
        for (int k = 0; k < NTAP; k++) s_wy[t][k] = wv[k + shift] * inv;
        s_by[t] = i0 + shift - IY0;
    }

    const float* Mp = mats + b * 6;
    const float M00 = __ldg(Mp + 0), M01 = __ldg(Mp + 1), M02 = __ldg(Mp + 2);
    const float M10 = __ldg(Mp + 3), M11 = __ldg(Mp + 4), M12 = __ldg(Mp + 5);

    const float* img = images + (size_t)b * IMG3F;

    // ---- Exact affine bbox of the warped tile's source footprint ----
    const float gy0 = (float)IY0, gy1 = (float)(IY0 + NIY - 1);
    const float gx0 = (float)IX0, gx1 = (float)(IX0 + NIX - 1);

    float sy00 = fmaf(M00, gy0, fmaf(M01, gx0, M02));
    float sy01 = fmaf(M00, gy0, fmaf(M01, gx1, M02));
    float sy10 = fmaf(M00, gy1, fmaf(M01, gx0, M02));
    float sy11 = fmaf(M00, gy1, fmaf(M01, gx1, M02));
    float sx00 = fmaf(M10, gy0, fmaf(M11, gx0, M12));
    float sx01 = fmaf(M10, gy0, fmaf(M11, gx1, M12));
    float sx10 = fmaf(M10, gy1, fmaf(M11, gx0, M12));
    float sx11 = fmaf(M10, gy1, fmaf(M11, gx1, M12));

    float symin = fminf(fminf(sy00, sy01), fminf(sy10, sy11));
    float symax = fmaxf(fmaxf(sy00, sy01), fmaxf(sy10, sy11));
    float sxmin = fminf(fminf(sx00, sx01), fminf(sx10, sx11));
    float sxmax = fmaxf(fmaxf(sx00, sx01), fmaxf(sx10, sx11));

    int fy0 = (int)floorf(symin) - 1;
    int fy1 = (int)floorf(symax) + 2;
    int fx0 = (int)floorf(sxmin) - 1;
    int fx1 = (int)floorf(sxmax) + 2;

    bool interior = (fy0 >= 0) && (fy1 < SRC_H) && (fx0 >= 0) && (fx1 < SRC_W);

    int by0 = max(0, fy0);
    int by1 = min(SRC_H - 1, fy1);
    int bx0 = max(0, fx0) & ~3;            // 4-px align for float4 staging
    int bx1 = min(SRC_W - 1, fx1);

    int hgt = by1 - by0 + 1;
    int wid = bx1 - bx0 + 1;
    bool staged = (hgt > 0) && (wid > 0) && (hgt <= SH_T) && (wid <= SW_PX);

    // ---- Stage source box: fp32 interleaved -> SMEM planar fp16 (RG half2 + B half) ----
    if (staged) {
        size_t base_f = (size_t)b * IMG3F + ((size_t)by0 * SRC_W + bx0) * NCH;
        for (int r = wrp; r < hgt; r += NW) {
            if (lane < 24) {                       // 24 lanes x 4 px = 96 px/row
                size_t fidx = base_f + (size_t)r * ROWF + (size_t)lane * 12;
                float f[12];
                if (fidx + 12 <= TOTF) {
                    const float4* g = (const float4*)(images + fidx);
                    float4 a = g[0], bq = g[1], cq = g[2];
                    f[0]=a.x; f[1]=a.y; f[2]=a.z; f[3]=a.w;
                    f[4]=bq.x; f[5]=bq.y; f[6]=bq.z; f[7]=bq.w;
                    f[8]=cq.x; f[9]=cq.y; f[10]=cq.z; f[11]=cq.w;
                } else {
                    #pragma unroll
                    for (int k = 0; k < 12; k++)
                        f[k] = (fidx + k < TOTF) ? images[fidx + k] : 0.0f;
                }
                uint4 rg;
                rg.x = h2u(__floats2half2_rn(f[0], f[1]));
                rg.y = h2u(__floats2half2_rn(f[3], f[4]));
                rg.z = h2u(__floats2half2_rn(f[6], f[7]));
                rg.w = h2u(__floats2half2_rn(f[9], f[10]));
                uint2 bb;
                bb.x = h2u(__floats2half2_rn(f[2], f[5]));
                bb.y = h2u(__floats2half2_rn(f[8], f[11]));
                *(uint4*)(s_RG + r * SW_PX + lane * 4) = rg;
                *(uint2*)(s_B  + r * SW_PX + lane * 4) = bb;
            }
        }
    }
    __syncthreads();

    // ---- Stage 1: warped tile -> packed uint2 (RG half2 | B half dup) ----
    const float by0f = (float)by0;
    const float bx0f = (float)bx0;

    for (int ty = wrp; ty < NIY; ty += NW) {
        float gy = (float)(IY0 + ty);
        float sybA = fmaf(M00, gy, M02);               // absolute bases
        float sxbA = fmaf(M10, gy, M12);

        if (staged && interior) {
            float sybR = sybA - by0f;
            float sxbR = sxbA - bx0f;
            #pragma unroll
            for (int c = 0; c < 3; c++) {
                int tx = c * 32 + lane;
                if (tx < NIX) {
                    float gx = (float)(IX0 + tx);
                    float syr = fmaf(M01, gx, sybR);
                    float sxr = fmaf(M11, gx, sxbR);
                    float fy = floorf(syr), fxx = floorf(sxr);
                    float ay = syr - fy,   ax = sxr - fxx;
                    int iy = (int)fy, ix = (int)fxx;

                    float oy_ = 1.0f - ay, oxx = 1.0f - ax;
                    float w00 = oy_ * oxx, w01 = oy_ * ax;
                    float w10 = ay * oxx,  w11 = ay * ax;

                    const __half2* r0 = s_RG + iy * SW_PX + ix;
                    __half2 q00 = r0[0], q01 = r0[1];
                    __half2 q10 = r0[SW_PX], q11 = r0[SW_PX + 1];
                    const __half* rb = s_B + iy * SW_PX + ix;
                    __half2 hb0 = __halves2half2(rb[0], rb[1]);
                    __half2 hb1 = __halves2half2(rb[SW_PX], rb[SW_PX + 1]);

                    __half2 aRG = __hmul2(__float2half2_rn(w00), q00);
                    aRG = __hfma2(__float2half2_rn(w01), q01, aRG);
                    aRG = __hfma2(__float2half2_rn(w10), q10, aRG);
                    aRG = __hfma2(__float2half2_rn(w11), q11, aRG);

                    __half2 hw0 = __floats2half2_rn(w00, w01);
                    __half2 hw1 = __floats2half2_rn(w10, w11);
                    __half2 hacc = __hfma2(hw1, hb1, __hmul2(hw0, hb0));
                    __half bl_h = __hadd(__low2half(hacc), __high2half(hacc));

                    uint2 px;
                    px.x = h2u(aRG);
                    px.y = h2u(__half2half2(bl_h));
                    s_wPX[ty * WPITCH + skew(tx)] = px;
                }
            }
        } else if (staged) {
            // border tile: validity-zeroed weights + clamped in-box indices
            #pragma unroll
            for (int c = 0; c < 3; c++) {
                int tx = c * 32 + lane;
                if (tx < NIX) {
                    float gx = (float)(IX0 + tx);
                    float sy = fmaf(M01, gx, sybA);
                    float sx = fmaf(M11, gx, sxbA);
                    float fy = floorf(sy), fxx = floorf(sx);
                    float ay = sy - fy,   ax = sx - fxx;
                    int iy = (int)fy, ix = (int)fxx;
                    int iy1 = iy + 1, ix1 = ix + 1;

                    float wy0 = ((unsigned)iy  < (unsigned)SRC_H) ? (1.0f - ay) : 0.0f;
                    float wy1 = ((unsigned)iy1 < (unsigned)SRC_H) ? ay : 0.0f;
                    float wx0v = ((unsigned)ix  < (unsigned)SRC_W) ? (1.0f - ax) : 0.0f;
                    float wx1v = ((unsigned)ix1 < (unsigned)SRC_W) ? ax : 0.0f;
                    float w00 = wy0 * wx0v, w01 = wy0 * wx1v;
                    float w10 = wy1 * wx0v, w11 = wy1 * wx1v;

                    int ry0 = min(max(iy  - by0, 0), hgt - 1);
                    int ry1 = min(max(iy1 - by0, 0), hgt - 1);
                    int rx0 = min(max(ix  - bx0, 0), wid - 1);
                    int rx1 = min(max(ix1 - bx0, 0), wid - 1);

                    __half2 q00 = s_RG[ry0 * SW_PX + rx0];
                    __half2 q01 = s_RG[ry0 * SW_PX + rx1];
                    __half2 q10 = s_RG[ry1 * SW_PX + rx0];
                    __half2 q11 = s_RG[ry1 * SW_PX + rx1];
                    __half2 hb0 = __halves2half2(s_B[ry0 * SW_PX + rx0], s_B[ry0 * SW_PX + rx1]);
                    __half2 hb1 = __halves2half2(s_B[ry1 * SW_PX + rx0], s_B[ry1 * SW_PX + rx1]);

                    __half2 aRG = __hmul2(__float2half2_rn(w00), q00);
                    aRG = __hfma2(__float2half2_rn(w01), q01, aRG);
                    aRG = __hfma2(__float2half2_rn(w10), q10, aRG);
                    aRG = __hfma2(__float2half2_rn(w11), q11, aRG);

                    __half2 hw0 = __floats2half2_rn(w00, w01);
                    __half2 hw1 = __floats2half2_rn(w10, w11);
                    __half2 hacc = __hfma2(hw1, hb1, __hmul2(hw0, hb0));
                    __half bl_h = __hadd(__low2half(hacc), __high2half(hacc));

                    uint2 px;
                    px.x = h2u(aRG);
                    px.y = h2u(__half2half2(bl_h));
                    s_wPX[ty * WPITCH + skew(tx)] = px;
                }
            }
        } else {
            // fallback: global fp32 gather (correctness safety net)
            #pragma unroll 1
            for (int c = 0; c < 3; c++) {
                int tx = c * 32 + lane;
                if (tx < NIX) {
                    float gx = (float)(IX0 + tx);
                    float sy = fmaf(M01, gx, sybA);
                    float sx = fmaf(M11, gx, sxbA);
                    float fy = floorf(sy), fxx = floorf(sx);
                    float ay = sy - fy,   ax = sx - fxx;
                    int iy = (int)fy, ix = (int)fxx;
                    int iy1 = iy + 1, ix1 = ix + 1;

                    float wy0 = ((unsigned)iy  < (unsigned)SRC_H) ? (1.0f - ay) : 0.0f;
                    float wy1 = ((unsigned)iy1 < (unsigned)SRC_H) ? ay : 0.0f;
                    float wx0v = ((unsigned)ix  < (unsigned)SRC_W) ? (1.0f - ax) : 0.0f;
                    float wx1v = ((unsigned)ix1 < (unsigned)SRC_W) ? ax : 0.0f;
                    float w00 = wy0 * wx0v, w01 = wy0 * wx1v;
                    float w10 = wy1 * wx0v, w11 = wy1 * wx1v;

                    int cy0 = min(max(iy, 0), SRC_H - 1);
                    int cy1 = min(max(iy1, 0), SRC_H - 1);
                    int cx0 = min(max(ix, 0), SRC_W - 1);
                    int cx1 = min(max(ix1, 0), SRC_W - 1);
                    const float* p00 = img + ((size_t)cy0 * SRC_W + cx0) * NCH;
                    const float* p01 = img + ((size_t)cy0 * SRC_W + cx1) * NCH;
                    const float* p10 = img + ((size_t)cy1 * SRC_W + cx0) * NCH;
                    const float* p11 = img + ((size_t)cy1 * SRC_W + cx1) * NCH;
                    float r  = w00 * p00[0] + w01 * p01[0] + w10 * p10[0] + w11 * p11[0];
                    float g  = w00 * p00[1] + w01 * p01[1] + w10 * p10[1] + w11 * p11[1];
                    float bl = w00 * p00[2] + w01 * p01[2] + w10 * p10[2] + w11 * p11[2];

                    uint2 px;
                    px.x = h2u(__floats2half2_rn(r, g));
                    px.y = h2u(__float2half2_rn(bl));
                    s_wPX[ty * WPITCH + skew(tx)] = px;
                }
            }
        }
    }
    __syncthreads();

    // ---- Stage 2: x-convolution (5 taps, fp32 accum, packed skewed I/O) ----
    {
        int ox  = tid & 31;                 // invariant across iterations
        int base = s_bx[ox];
        float w0 = s_wx[ox][0], w1 = s_wx[ox][1], w2 = s_wx[ox][2];
        float w3 = s_wx[ox][3], w4 = s_wx[ox][4];
        for (int ty = tid >> 5; ty < NIY; ty += NW) {
            const uint2* row = s_wPX + ty * WPITCH;
            float a0 = 0.0f, a1 = 0.0f, a2 = 0.0f;
            #pragma unroll
            for (int k = 0; k < NTAP; k++) {
                float w = (k == 0) ? w0 : (k == 1) ? w1 : (k == 2) ? w2
                        : (k == 3) ? w3 : w4;
                uint2 px = row[skew(base + k)];
                float2 f = __half22float2(u2h(px.x));
                a0 = fmaf(w, f.x, a0);
                a1 = fmaf(w, f.y, a1);
                a2 = fmaf(w, __half2float(__low2half(u2h(px.y))), a2);
            }
            uint2 tv;
            tv.x = h2u(__floats2half2_rn(a0, a1));
            tv.y = h2u(__float2half2_rn(a2));
            s_t[skew(ty * TOX + ox)] = tv;
        }
    }
    __syncthreads();

    // ---- Stage 3: y-convolution (5 taps, fp32 accum, packed skewed reads) + store ----
    {
        int ox = tid & 31;
        for (int oy = tid >> 5; oy < TOY; oy += NW) {
            int base = s_by[oy];
            float a0 = 0.0f, a1 = 0.0f, a2 = 0.0f;
            #pragma unroll
            for (int k = 0; k < NTAP; k++) {
                float w = s_wy[oy][k];
                uint2 tv = s_t[skew((base + k) * TOX + ox)];
                float2 f = __half22float2(u2h(tv.x));
                a0 = fmaf(w, f.x, a0);
                a1 = fmaf(w, f.y, a1);
                a2 = fmaf(w, __half2float(__low2half(u2h(tv.y))), a2);
            }
            float* op = out + (((size_t)b * OUT_N + (oy0 + oy)) * OUT_N + (ox0 + ox)) * NCH;
            op[0] = a0;
            op[1] = a1;
            op[2] = a2;
        }
    }
}

extern "C" void kernel_launch(void* const* d_in, const int* in_sizes, int n_in,
                              void* d_out, int out_size)
{
    const float* images = (const float*)d_in[0];
    const float* mats   = (const float*)d_in[1];
    float* out = (float*)d_out;

    cudaFuncSetAttribute(warp_resize_kernel,
                         cudaFuncAttributeMaxDynamicSharedMemorySize, DYN_BYTES);

    dim3 grid(OUT_N / TOX, OUT_N / TOY, 32);   // 7 x 16 x 32
    warp_resize_kernel<<<grid, NTHREADS, DYN_BYTES>>>(images, mats, out);
}